// round 2
// baseline (speedup 1.0000x reference)
#include <cuda_runtime.h>

#define NIMG 1024          // B*R = 16*64
#define KC_THREADS 384
#define KC_ACTIVE 364      // 2 ocg * 26 rows * 7 colgroups

// ---- scratch (static device arrays: no allocation allowed) ----
__device__ float g_pooled1[NIMG * 64 * 30 * 30];   // conv1+pool1 output, [img][c][30][30]
__device__ int   g_bounds[NIMG][2][4];             // per pair, per channel: jx1 jx2 iy1 iy2
__device__ float g_w2t[64 * 25 * 32];              // conv2 weights transposed: [c][dy][dx][oc]

// ---------------- packed f32x2 helpers ----------------
__device__ __forceinline__ unsigned long long fma2(unsigned long long a,
                                                   unsigned long long b,
                                                   unsigned long long c) {
    unsigned long long d;
    asm("fma.rn.f32x2 %0, %1, %2, %3;" : "=l"(d) : "l"(a), "l"(b), "l"(c));
    return d;
}
__device__ __forceinline__ unsigned long long dup2(float v) {
    unsigned long long d;
    asm("mov.b64 %0, {%1, %1};" : "=l"(d) : "f"(v));
    return d;
}
__device__ __forceinline__ float2 u2f(unsigned long long u) {
    float2 f;
    asm("mov.b64 {%0, %1}, %2;" : "=f"(f.x), "=f"(f.y) : "l"(u));
    return f;
}

// ---------------- Kernel A: integer rect bounds per (pair, channel) ----------------
__global__ void k_bounds(const float* __restrict__ bboxes,
                         const int*   __restrict__ pairs) {
    int n = blockIdx.x * blockDim.x + threadIdx.x;
    if (n >= NIMG) return;
    int b  = n >> 6;                 // R = 64
    int p0 = pairs[n * 2 + 0];
    int p1 = pairs[n * 2 + 1];
    const float* B0 = bboxes + (b * 32 + p0) * 4;
    const float* B1 = bboxes + (b * 32 + p1) * 4;
    float bx1[2] = {B0[0], B1[0]}, by1[2] = {B0[1], B1[1]};
    float bx2[2] = {B0[2], B1[2]}, by2[2] = {B0[3], B1[3]};
    float ux1 = fminf(bx1[0], bx1[1]), uy1 = fminf(by1[0], by1[1]);
    float ux2 = fmaxf(bx2[0], bx2[1]), uy2 = fmaxf(by2[0], by2[1]);
    float uw = fmaxf(ux2 - ux1, 1e-6f), uh = fmaxf(uy2 - uy1, 1e-6f);
    for (int c = 0; c < 2; ++c) {
        float x1 = (bx1[c] - ux1) / uw * 64.0f;
        float y1 = (by1[c] - uy1) / uh * 64.0f;
        float x2 = (bx2[c] - ux1) / uw * 64.0f;
        float y2 = (by2[c] - uy1) / uh * 64.0f;
        int jlo = 64, jhi = -1, ilo = 64, ihi = -1;
        for (int k = 0; k < 64; ++k) {
            float f = (float)k + 0.5f;
            if (f >= x1 && f <= x2) { if (k < jlo) jlo = k; jhi = k; }
            if (f >= y1 && f <= y2) { if (k < ilo) ilo = k; ihi = k; }
        }
        g_bounds[n][c][0] = jlo; g_bounds[n][c][1] = jhi;
        g_bounds[n][c][2] = ilo; g_bounds[n][c][3] = ihi;
    }
}

// ---------------- Kernel A2: transpose conv2 weights to [c][dy][dx][oc] ----------------
__global__ void k_wtrans(const float* __restrict__ w2) {
    int i = blockIdx.x * blockDim.x + threadIdx.x;
    if (i >= 64 * 25 * 32) return;
    int oc = i & 31;
    int rest = i >> 5;
    int dx = rest % 5;
    int r2 = rest / 5;
    int dy = r2 % 5;
    int c  = r2 / 5;
    g_w2t[i] = w2[((oc * 64 + c) * 5 + dy) * 5 + dx];
}

// ---------------- Kernel B: conv1 + bias + maxpool2 via 2D weight prefix sums ----------------
__global__ void k_conv1pool(const float* __restrict__ w1,
                            const float* __restrict__ b1) {
    __shared__ float P[64 * 2 * 36];     // [o][c][6][6] prefix
    __shared__ float bias[64];
    __shared__ int wy[2][60], wx[2][60]; // packed window codes: lo | (hiEx<<4)
    int img = blockIdx.x, t = threadIdx.x;

    if (t < 128) {
        int o = t >> 1, c = t & 1;
        float wloc[25];
#pragma unroll
        for (int k = 0; k < 25; ++k) wloc[k] = w1[(o * 2 + c) * 25 + k];
        float* Pt = &P[(o * 2 + c) * 36];
#pragma unroll
        for (int bb = 0; bb < 6; ++bb) Pt[bb] = 0.0f;
#pragma unroll
        for (int a = 1; a < 6; ++a) {
            Pt[a * 6] = 0.0f;
            float rs = 0.0f;
#pragma unroll
            for (int bb = 1; bb < 6; ++bb) {
                rs += wloc[(a - 1) * 5 + (bb - 1)];
                Pt[a * 6 + bb] = Pt[(a - 1) * 6 + bb] + rs;
            }
        }
    }
    if (t < 64) bias[t] = b1[t];
    if (t < 240) {
        int c = t & 1;
        int rest = t >> 1;
        int pos = rest % 60;
        int dim = rest / 60;
        int lo = g_bounds[img][c][dim ? 2 : 0];
        int hi = g_bounds[img][c][dim ? 3 : 1];
        int l = lo - pos;      l = max(0, min(5, l));
        int h = hi + 1 - pos;  h = max(l, min(5, h));
        int code = l | (h << 4);
        if (dim) wy[c][pos] = code; else wx[c][pos] = code;
    }
    __syncthreads();

    float* outp = g_pooled1 + (size_t)img * 57600;
    for (int idx = t; idx < 57600; idx += 256) {
        int o = idx / 900;
        int r = idx - o * 900;
        int I = r / 30, J = r - I * 30;
        const float* P0 = &P[o * 72];
        const float* P1 = P0 + 36;
        float bo = bias[o];
        float m = -1e30f;
#pragma unroll
        for (int iy = 0; iy < 2; ++iy) {
            int i = 2 * I + iy;
            int cy0 = wy[0][i], cy1 = wy[1][i];
#pragma unroll
            for (int jx = 0; jx < 2; ++jx) {
                int j = 2 * J + jx;
                int cx0 = wx[0][j], cx1 = wx[1][j];
                float v = bo;
                {
                    int yl = cy0 & 15, yh = cy0 >> 4, xl = cx0 & 15, xh = cx0 >> 4;
                    v += P0[yh * 6 + xh] - P0[yl * 6 + xh] - P0[yh * 6 + xl] + P0[yl * 6 + xl];
                }
                {
                    int yl = cy1 & 15, yh = cy1 >> 4, xl = cx1 & 15, xh = cx1 >> 4;
                    v += P1[yh * 6 + xh] - P1[yl * 6 + xh] - P1[yh * 6 + xl] + P1[yl * 6 + xl];
                }
                m = fmaxf(m, v);
            }
        }
        outp[idx] = m;
    }
}

// ---------------- Kernel C: conv2 + bias + maxpool2 + mean + fc + relu (fused) ----------------
// One CTA per image. Retiled: each active thread owns 16 out-channels x 4 out-cols
// (1 row), output cols padded 26->28 (cols 26,27 computed then discarded).
// Each weight LDS.128 now feeds 8 FFMA2 (was 4); inputs loaded once per (cc,dy).
__global__ void __launch_bounds__(KC_THREADS, 1)
k_conv2tail(const float* __restrict__ b2,
            const float* __restrict__ fcw,
            const float* __restrict__ fcb,
            float* __restrict__ out) {
    extern __shared__ float sh[];
    float* ins = sh;             // 32 * 30 * 32 = 30720 floats (x-stride 32, cols 30,31 zero)
    float* ws  = sh + 30720;     // 32 * 25 * 32 = 25600 floats, [cc][dy][dx][oc]
    __shared__ float sfeat[32];
    __shared__ float sb2[32];

    int img = blockIdx.x, t = threadIdx.x;
    if (t < 32) sb2[t] = b2[t];
    bool act = t < KC_ACTIVE;
    int ocg = t / 182;                 // 0..1 (16 oc each)
    int r   = t - ocg * 182;
    int orow = r / 7;                  // 0..25
    int colg = r - orow * 7;           // 0..6
    int j0   = colg * 4;               // output col base (0..24)

    unsigned long long acc[32];        // [wq 0..7][p 0..3]
#pragma unroll
    for (int q = 0; q < 32; ++q) acc[q] = 0ull;

    for (int cg = 0; cg < 2; ++cg) {
        __syncthreads();   // previous chunk's compute done before overwrite
        // fill 32-channel input chunk: rows padded to 32 floats, cols 30,31 zeroed
        const float2* src = (const float2*)(g_pooled1 + (size_t)img * 57600 + cg * 28800);
        for (int i2 = t; i2 < 15360; i2 += KC_THREADS) {
            int x2 = i2 & 15;                 // float2 index within padded row (16 per row)
            int rest = i2 >> 4;
            int y  = rest % 30;
            int cc = rest / 30;
            float2 v = (x2 < 15) ? src[cc * 450 + y * 15 + x2] : make_float2(0.f, 0.f);
            *(float2*)(ins + cc * 960 + y * 32 + x2 * 2) = v;
        }
        // load weight chunk (contiguous, float4)
        const float4* wsrc = (const float4*)(g_w2t + cg * 25600);
        float4* wdst = (float4*)ws;
        for (int i4 = t; i4 < 6400; i4 += KC_THREADS) wdst[i4] = wsrc[i4];
        __syncthreads();

        if (act) {
#pragma unroll 1
            for (int cc = 0; cc < 32; ++cc) {
                const float* inc = ins + cc * 960 + orow * 32 + j0;
                const float* wcc = ws + cc * 800 + ocg * 16;
#pragma unroll
                for (int dy = 0; dy < 5; ++dy) {
                    const float2* vp = (const float2*)(inc + dy * 32);
                    float2 v0 = vp[0], v1 = vp[1], v2 = vp[2], v3 = vp[3];
                    unsigned long long d[8];
                    d[0] = dup2(v0.x); d[1] = dup2(v0.y);
                    d[2] = dup2(v1.x); d[3] = dup2(v1.y);
                    d[4] = dup2(v2.x); d[5] = dup2(v2.y);
                    d[6] = dup2(v3.x); d[7] = dup2(v3.y);
#pragma unroll
                    for (int dx = 0; dx < 5; ++dx) {
                        const ulonglong2* wp =
                            (const ulonglong2*)(wcc + (dy * 5 + dx) * 32);
                        ulonglong2 wa = wp[0], wb = wp[1], wc2 = wp[2], wd = wp[3];
                        unsigned long long w[8] = {wa.x, wa.y, wb.x, wb.y,
                                                   wc2.x, wc2.y, wd.x, wd.y};
#pragma unroll
                        for (int wq = 0; wq < 8; ++wq) {
#pragma unroll
                            for (int p = 0; p < 4; ++p)
                                acc[wq * 4 + p] =
                                    fma2(d[dx + p], w[wq], acc[wq * 4 + p]);
                        }
                    }
                }
            }
        }
    }

    // ---- pool2 (2x2 max) + mean(13x13) + conv2 bias ----
    __syncthreads();
    float* red = sh;   // reuse: [26 rows][14 col-pairs][32 oc] = 11648 floats
    if (act) {
        int pj0 = colg * 2;
#pragma unroll
        for (int wq = 0; wq < 8; ++wq) {
            float2 a = u2f(acc[wq * 4 + 0]);
            float2 b = u2f(acc[wq * 4 + 1]);
            float2 c = u2f(acc[wq * 4 + 2]);
            float2 e = u2f(acc[wq * 4 + 3]);
            int oc = ocg * 16 + wq * 2;
            red[(orow * 14 + pj0) * 32 + oc]         = fmaxf(a.x, b.x);
            red[(orow * 14 + pj0) * 32 + oc + 1]     = fmaxf(a.y, b.y);
            red[(orow * 14 + pj0 + 1) * 32 + oc]     = fmaxf(c.x, e.x);
            red[(orow * 14 + pj0 + 1) * 32 + oc + 1] = fmaxf(c.y, e.y);
        }
    }
    __syncthreads();
    if (t < 32) {
        float s = 0.0f;
        for (int I = 0; I < 13; ++I) {
#pragma unroll
            for (int J = 0; J < 13; ++J) {
                float hi = red[((2 * I) * 14 + J) * 32 + t];
                float lo = red[((2 * I + 1) * 14 + J) * 32 + t];
                s += fmaxf(hi, lo);
            }
        }
        sfeat[t] = s * (1.0f / 169.0f) + sb2[t];
    }
    __syncthreads();

    // ---- fc 32 -> 512 + relu ----
    for (int o = t; o < 512; o += KC_THREADS) {
        const float4* wv = (const float4*)(fcw + o * 32);
        float s = fcb[o];
#pragma unroll
        for (int q = 0; q < 8; ++q) {
            float4 w = wv[q];
            s += w.x * sfeat[q * 4 + 0] + w.y * sfeat[q * 4 + 1]
               + w.z * sfeat[q * 4 + 2] + w.w * sfeat[q * 4 + 3];
        }
        out[(size_t)img * 512 + o] = fmaxf(s, 0.0f);
    }
}

// ---------------- launch ----------------
extern "C" void kernel_launch(void* const* d_in, const int* in_sizes, int n_in,
                              void* d_out, int out_size) {
    const float* bboxes = (const float*)d_in[0];
    const int*   pairs  = (const int*)d_in[3];
    const float* w1     = (const float*)d_in[4];
    const float* b1     = (const float*)d_in[5];
    const float* w2     = (const float*)d_in[6];
    const float* b2     = (const float*)d_in[7];
    const float* fcw    = (const float*)d_in[8];
    const float* fcb    = (const float*)d_in[9];
    float* out = (float*)d_out;

    k_bounds<<<4, 256>>>(bboxes, pairs);
    k_wtrans<<<50, 1024>>>(w2);
    k_conv1pool<<<NIMG, 256>>>(w1, b1);

    static const int kSmem = (30720 + 25600) * 4;   // 225,280 B
    cudaFuncSetAttribute(k_conv2tail, cudaFuncAttributeMaxDynamicSharedMemorySize, kSmem);
    k_conv2tail<<<NIMG, KC_THREADS, kSmem>>>(b2, fcw, fcb, out);
}

// round 3
// speedup vs baseline: 1.1013x; 1.1013x over previous
#include <cuda_runtime.h>

#define NIMG 1024          // B*R = 16*64
#define KC_THREADS 768
#define KC_R 182           // 26 rows * 7 colgroups

// ---- scratch (static device arrays: no allocation allowed) ----
__device__ float g_pooled1[NIMG * 64 * 30 * 30];   // conv1+pool1 output, [img][c][30][30]
__device__ int   g_bounds[NIMG][2][4];             // per pair, per channel: jx1 jx2 iy1 iy2
__device__ float g_w2t[64 * 25 * 32];              // conv2 weights transposed: [c][dy][dx][oc]

// ---------------- packed f32x2 helpers ----------------
__device__ __forceinline__ unsigned long long fma2(unsigned long long a,
                                                   unsigned long long b,
                                                   unsigned long long c) {
    unsigned long long d;
    asm("fma.rn.f32x2 %0, %1, %2, %3;" : "=l"(d) : "l"(a), "l"(b), "l"(c));
    return d;
}
__device__ __forceinline__ unsigned long long dup2(float v) {
    unsigned long long d;
    asm("mov.b64 %0, {%1, %1};" : "=l"(d) : "f"(v));
    return d;
}
__device__ __forceinline__ float2 u2f(unsigned long long u) {
    float2 f;
    asm("mov.b64 {%0, %1}, %2;" : "=f"(f.x), "=f"(f.y) : "l"(u));
    return f;
}

// ---------------- Kernel A: integer rect bounds per (pair, channel) ----------------
__global__ void k_bounds(const float* __restrict__ bboxes,
                         const int*   __restrict__ pairs) {
    int n = blockIdx.x * blockDim.x + threadIdx.x;
    if (n >= NIMG) return;
    int b  = n >> 6;                 // R = 64
    int p0 = pairs[n * 2 + 0];
    int p1 = pairs[n * 2 + 1];
    const float* B0 = bboxes + (b * 32 + p0) * 4;
    const float* B1 = bboxes + (b * 32 + p1) * 4;
    float bx1[2] = {B0[0], B1[0]}, by1[2] = {B0[1], B1[1]};
    float bx2[2] = {B0[2], B1[2]}, by2[2] = {B0[3], B1[3]};
    float ux1 = fminf(bx1[0], bx1[1]), uy1 = fminf(by1[0], by1[1]);
    float ux2 = fmaxf(bx2[0], bx2[1]), uy2 = fmaxf(by2[0], by2[1]);
    float uw = fmaxf(ux2 - ux1, 1e-6f), uh = fmaxf(uy2 - uy1, 1e-6f);
    for (int c = 0; c < 2; ++c) {
        float x1 = (bx1[c] - ux1) / uw * 64.0f;
        float y1 = (by1[c] - uy1) / uh * 64.0f;
        float x2 = (bx2[c] - ux1) / uw * 64.0f;
        float y2 = (by2[c] - uy1) / uh * 64.0f;
        int jlo = 64, jhi = -1, ilo = 64, ihi = -1;
        for (int k = 0; k < 64; ++k) {
            float f = (float)k + 0.5f;
            if (f >= x1 && f <= x2) { if (k < jlo) jlo = k; jhi = k; }
            if (f >= y1 && f <= y2) { if (k < ilo) ilo = k; ihi = k; }
        }
        g_bounds[n][c][0] = jlo; g_bounds[n][c][1] = jhi;
        g_bounds[n][c][2] = ilo; g_bounds[n][c][3] = ihi;
    }
}

// ---------------- Kernel A2: transpose conv2 weights to [c][dy][dx][oc] ----------------
__global__ void k_wtrans(const float* __restrict__ w2) {
    int i = blockIdx.x * blockDim.x + threadIdx.x;
    if (i >= 64 * 25 * 32) return;
    int oc = i & 31;
    int rest = i >> 5;
    int dx = rest % 5;
    int r2 = rest / 5;
    int dy = r2 % 5;
    int c  = r2 / 5;
    g_w2t[i] = w2[((oc * 64 + c) * 5 + dy) * 5 + dx];
}

// ---------------- Kernel B: conv1 + bias + maxpool2 via 2D weight prefix sums ----------------
// v2: 512 threads, per-pixel window offsets hoisted out of the o-loop.
__global__ void __launch_bounds__(512, 1)
k_conv1pool(const float* __restrict__ w1,
            const float* __restrict__ b1) {
    __shared__ float P[64 * 2 * 36];     // [o][c][6][6] prefix
    __shared__ float bias[64];
    __shared__ int wy[2][60], wx[2][60]; // packed window codes: lo | (hiEx<<4)
    int img = blockIdx.x, t = threadIdx.x;

    if (t < 128) {
        int o = t >> 1, c = t & 1;
        float wloc[25];
#pragma unroll
        for (int k = 0; k < 25; ++k) wloc[k] = w1[(o * 2 + c) * 25 + k];
        float* Pt = &P[(o * 2 + c) * 36];
#pragma unroll
        for (int bb = 0; bb < 6; ++bb) Pt[bb] = 0.0f;
#pragma unroll
        for (int a = 1; a < 6; ++a) {
            Pt[a * 6] = 0.0f;
            float rs = 0.0f;
#pragma unroll
            for (int bb = 1; bb < 6; ++bb) {
                rs += wloc[(a - 1) * 5 + (bb - 1)];
                Pt[a * 6 + bb] = Pt[(a - 1) * 6 + bb] + rs;
            }
        }
    }
    if (t < 64) bias[t] = b1[t];
    if (t < 240) {
        int c = t & 1;
        int rest = t >> 1;
        int pos = rest % 60;
        int dim = rest / 60;
        int lo = g_bounds[img][c][dim ? 2 : 0];
        int hi = g_bounds[img][c][dim ? 3 : 1];
        int l = lo - pos;      l = max(0, min(5, l));
        int h = hi + 1 - pos;  h = max(l, min(5, h));
        int code = l | (h << 4);
        if (dim) wy[c][pos] = code; else wx[c][pos] = code;
    }
    __syncthreads();

    float* outp = g_pooled1 + (size_t)img * 57600;
#pragma unroll
    for (int p = 0; p < 2; ++p) {
        int pix = t + p * 512;
        if (pix >= 900) break;
        int I = pix / 30, J = pix - I * 30;
        // hoist window corner offsets for both channels, both subrows/subcols
        int yl6[2][2], yh6[2][2], xl[2][2], xh[2][2];
#pragma unroll
        for (int c = 0; c < 2; ++c) {
#pragma unroll
            for (int s = 0; s < 2; ++s) {
                int cy = wy[c][2 * I + s];
                yl6[c][s] = (cy & 15) * 6; yh6[c][s] = (cy >> 4) * 6;
                int cx = wx[c][2 * J + s];
                xl[c][s] = cx & 15; xh[c][s] = cx >> 4;
            }
        }
        const float* Pb = P;
        for (int o = 0; o < 64; ++o, Pb += 72) {
            float m = -1e30f;
#pragma unroll
            for (int iy = 0; iy < 2; ++iy) {
#pragma unroll
                for (int jx = 0; jx < 2; ++jx) {
                    float v = bias[o];
#pragma unroll
                    for (int c = 0; c < 2; ++c) {
                        const float* Pc = Pb + c * 36;
                        v += Pc[yh6[c][iy] + xh[c][jx]] - Pc[yl6[c][iy] + xh[c][jx]]
                           - Pc[yh6[c][iy] + xl[c][jx]] + Pc[yl6[c][iy] + xl[c][jx]];
                    }
                    m = fmaxf(m, v);
                }
            }
            outp[o * 900 + pix] = m;
        }
    }
}

// ---------------- Kernel C: conv2 + bias + maxpool2 + mean + fc + relu (fused) ----------------
// One CTA per image, 768 threads (24 warps). Each active thread: 8 oc x 4 out-cols x 1 row.
// 4 channel chunks of 16; smem = ins(61440B) + ws(51200B) = 112,640B.
// Thread layout t = r*4 + ocg: lanes share input addrs (broadcast), weights contiguous.
__global__ void __launch_bounds__(KC_THREADS, 1)
k_conv2tail(const float* __restrict__ b2,
            const float* __restrict__ fcw,
            const float* __restrict__ fcb,
            float* __restrict__ out) {
    extern __shared__ float sh[];
    float* ins = sh;             // 16 * 30 * 32 = 15360 floats (x-stride 32, cols 30,31 zero)
    float* ws  = sh + 15360;     // 16 * 25 * 32 = 12800 floats, [cc][dy][dx][oc]
    __shared__ float sfeat[32];
    __shared__ float sb2[32];

    int img = blockIdx.x, t = threadIdx.x;
    if (t < 32) sb2[t] = b2[t];
    int ocg = t & 3;                   // 0..3 (8 oc each)
    int r   = t >> 2;                  // 0..191
    bool act = r < KC_R;
    int orow = r / 7;                  // 0..25
    int colg = r - orow * 7;           // 0..6
    int j0   = colg * 4;               // output col base (0..24)

    unsigned long long acc[16];        // [wq 0..3][p 0..3]
#pragma unroll
    for (int q = 0; q < 16; ++q) acc[q] = 0ull;

    for (int cg = 0; cg < 4; ++cg) {
        __syncthreads();   // previous chunk's compute done before overwrite
        // fill 16-channel input chunk: rows padded to 32 floats, cols 30,31 zeroed
        const float2* src = (const float2*)(g_pooled1 + (size_t)img * 57600 + cg * 14400);
        for (int i2 = t; i2 < 7680; i2 += KC_THREADS) {
            int x2 = i2 & 15;                 // float2 index in padded row
            int rest = i2 >> 4;
            int y  = rest % 30;
            int cc = rest / 30;
            float2 v = (x2 < 15) ? src[cc * 450 + y * 15 + x2] : make_float2(0.f, 0.f);
            *(float2*)(ins + cc * 960 + y * 32 + x2 * 2) = v;
        }
        // load weight chunk (contiguous, float4)
        const float4* wsrc = (const float4*)(g_w2t + cg * 12800);
        float4* wdst = (float4*)ws;
        for (int i4 = t; i4 < 3200; i4 += KC_THREADS) wdst[i4] = wsrc[i4];
        __syncthreads();

        if (act) {
#pragma unroll 1
            for (int cc = 0; cc < 16; ++cc) {
                const float* inc = ins + cc * 960 + orow * 32 + j0;
                const float* wcc = ws + cc * 800 + ocg * 8;
#pragma unroll
                for (int dy = 0; dy < 5; ++dy) {
                    const float4* vp = (const float4*)(inc + dy * 32);
                    float4 va = vp[0], vb = vp[1];
                    unsigned long long d[8];
                    d[0] = dup2(va.x); d[1] = dup2(va.y);
                    d[2] = dup2(va.z); d[3] = dup2(va.w);
                    d[4] = dup2(vb.x); d[5] = dup2(vb.y);
                    d[6] = dup2(vb.z); d[7] = dup2(vb.w);
#pragma unroll
                    for (int dx = 0; dx < 5; ++dx) {
                        const ulonglong2* wp =
                            (const ulonglong2*)(wcc + (dy * 5 + dx) * 32);
                        ulonglong2 w0 = wp[0], w1 = wp[1];
                        unsigned long long w[4] = {w0.x, w0.y, w1.x, w1.y};
#pragma unroll
                        for (int wq = 0; wq < 4; ++wq) {
#pragma unroll
                            for (int p = 0; p < 4; ++p)
                                acc[wq * 4 + p] =
                                    fma2(d[dx + p], w[wq], acc[wq * 4 + p]);
                        }
                    }
                }
            }
        }
    }

    // ---- pool2 (2x2 max) + mean(13x13) + conv2 bias ----
    __syncthreads();
    float* red = sh;   // reuse: [26 rows][14 col-pairs][32 oc] = 11648 floats
    if (act) {
        int pj0 = colg * 2;
#pragma unroll
        for (int wq = 0; wq < 4; ++wq) {
            float2 a = u2f(acc[wq * 4 + 0]);
            float2 b = u2f(acc[wq * 4 + 1]);
            float2 c = u2f(acc[wq * 4 + 2]);
            float2 e = u2f(acc[wq * 4 + 3]);
            int oc = ocg * 8 + wq * 2;
            red[(orow * 14 + pj0) * 32 + oc]         = fmaxf(a.x, b.x);
            red[(orow * 14 + pj0) * 32 + oc + 1]     = fmaxf(a.y, b.y);
            red[(orow * 14 + pj0 + 1) * 32 + oc]     = fmaxf(c.x, e.x);
            red[(orow * 14 + pj0 + 1) * 32 + oc + 1] = fmaxf(c.y, e.y);
        }
    }
    __syncthreads();
    if (t < 32) {
        float s = 0.0f;
        for (int I = 0; I < 13; ++I) {
#pragma unroll
            for (int J = 0; J < 13; ++J) {
                float hi = red[((2 * I) * 14 + J) * 32 + t];
                float lo = red[((2 * I + 1) * 14 + J) * 32 + t];
                s += fmaxf(hi, lo);
            }
        }
        sfeat[t] = s * (1.0f / 169.0f) + sb2[t];
    }
    __syncthreads();

    // ---- fc 32 -> 512 + relu ----
    if (t < 512) {
        int o = t;
        const float4* wv = (const float4*)(fcw + o * 32);
        float s = fcb[o];
#pragma unroll
        for (int q = 0; q < 8; ++q) {
            float4 w = wv[q];
            s += w.x * sfeat[q * 4 + 0] + w.y * sfeat[q * 4 + 1]
               + w.z * sfeat[q * 4 + 2] + w.w * sfeat[q * 4 + 3];
        }
        out[(size_t)img * 512 + o] = fmaxf(s, 0.0f);
    }
}

// ---------------- launch ----------------
extern "C" void kernel_launch(void* const* d_in, const int* in_sizes, int n_in,
                              void* d_out, int out_size) {
    const float* bboxes = (const float*)d_in[0];
    const int*   pairs  = (const int*)d_in[3];
    const float* w1     = (const float*)d_in[4];
    const float* b1     = (const float*)d_in[5];
    const float* w2     = (const float*)d_in[6];
    const float* b2     = (const float*)d_in[7];
    const float* fcw    = (const float*)d_in[8];
    const float* fcb    = (const float*)d_in[9];
    float* out = (float*)d_out;

    k_bounds<<<4, 256>>>(bboxes, pairs);
    k_wtrans<<<50, 1024>>>(w2);
    k_conv1pool<<<NIMG, 512>>>(w1, b1);

    static const int kSmem = (15360 + 12800) * 4;   // 112,640 B
    cudaFuncSetAttribute(k_conv2tail, cudaFuncAttributeMaxDynamicSharedMemorySize, kSmem);
    k_conv2tail<<<NIMG, KC_THREADS, kSmem>>>(b2, fcw, fcb, out);
}